// round 13
// baseline (speedup 1.0000x reference)
#include <cuda_runtime.h>

#define N_NODES 50000
#define N_EDGES 800000
#define E_TOT   850000
#define F_IN    128
#define H1      4
#define HC1     256
#define C2      64
#define NGRAPH  500
#define NCLS    10
#define NEG     0.2f

// ---------------- scratch (device globals; no allocation allowed) ----------------
__device__ __align__(16) float g_h1[N_NODES * HC1];
__device__ __align__(16) float g_out1[N_NODES * HC1];
__device__ __align__(16) float g_als1[N_NODES * H1];
__device__ __align__(16) float g_ald1[N_NODES * H1];

__device__ __align__(16) float g_h2[N_NODES * C2];
__device__ __align__(16) float g_als2[N_NODES];
__device__ __align__(16) float g_ald2[N_NODES];

__device__ __align__(16) float g_pool[NGRAPH * C2];
__device__ int g_cnt[NGRAPH];

// CSR by destination
__device__ int g_deg[N_NODES];
__device__ int g_ptr[N_NODES + 1];
__device__ int g_fill[N_NODES];
__device__ int g_csr[E_TOT];

__device__ __forceinline__ void red_add_v2(float* addr, float a, float b) {
    asm volatile("red.global.add.v2.f32 [%0], {%1,%2};"
                 :: "l"(addr), "f"(a), "f"(b) : "memory");
}
__device__ __forceinline__ float lrelu(float e) { return e > 0.f ? e : NEG * e; }

// ---- packed f32x2 helpers (sm_100+) ----
__device__ __forceinline__ unsigned long long pk2(float lo, float hi) {
    unsigned long long r;
    asm("mov.b64 %0, {%1,%2};" : "=l"(r) : "f"(lo), "f"(hi));
    return r;
}
__device__ __forceinline__ float2 upk2(unsigned long long v) {
    float2 r;
    asm("mov.b64 {%0,%1}, %2;" : "=f"(r.x), "=f"(r.y) : "l"(v));
    return r;
}
__device__ __forceinline__ void ffma2(unsigned long long& acc, unsigned long long a,
                                      unsigned long long b) {
    asm("fma.rn.f32x2 %0, %1, %2, %0;" : "+l"(acc) : "l"(a), "l"(b));
}

// ---------------- init: zero degree + pool + cnt ----------------
__global__ void k_init() {
    int idx = blockIdx.x * blockDim.x + threadIdx.x;
    if (idx < N_NODES) g_deg[idx] = 0;
    if (idx < NGRAPH * C2) g_pool[idx] = 0.f;
    if (idx < NGRAPH) g_cnt[idx] = 0;
}

// ---------------- CSR build + per-graph node counts ----------------
__global__ void k_deg(const int* __restrict__ ei, const int* __restrict__ bat) {
    int idx = blockIdx.x * blockDim.x + threadIdx.x;
    if (idx < N_NODES) atomicAdd(&g_cnt[bat[idx]], 1);
    if (idx >= E_TOT) return;
    int d = (idx < N_EDGES) ? ei[N_EDGES + idx] : (idx - N_EDGES);
    atomicAdd(&g_deg[d], 1);
}

// ---------------- scan: thread-coarsened single block ----------------
#define SCAN_T 1024
#define SCHUNK ((N_NODES + SCAN_T - 1) / SCAN_T)   // 49
__global__ void k_scan() {
    __shared__ int sm[SCAN_T];
    int t = threadIdx.x;
    int base = t * SCHUNK;
    int loc = 0;
    for (int j = 0; j < SCHUNK; j++) {
        int i = base + j;
        if (i < N_NODES) loc += g_deg[i];
    }
    sm[t] = loc;
    __syncthreads();
#pragma unroll
    for (int off = 1; off < SCAN_T; off <<= 1) {
        int u = (t >= off) ? sm[t - off] : 0;
        __syncthreads();
        sm[t] += u;
        __syncthreads();
    }
    int run = sm[t] - loc;   // exclusive prefix of this chunk
    for (int j = 0; j < SCHUNK; j++) {
        int i = base + j;
        if (i < N_NODES) {
            int v = g_deg[i];
            g_ptr[i] = run;
            g_fill[i] = run;
            run += v;
        }
    }
    if (t == SCAN_T - 1) g_ptr[N_NODES] = sm[t];
}

__global__ void k_fill(const int* __restrict__ ei) {
    int idx = blockIdx.x * blockDim.x + threadIdx.x;
    if (idx >= E_TOT) return;
    int s, d;
    if (idx < N_EDGES) { s = ei[idx]; d = ei[N_EDGES + idx]; }
    else               { s = idx - N_EDGES; d = s; }
    int pos = atomicAdd(&g_fill[d], 1);
    g_csr[pos] = s;
}

// ---------------- GEMM1: h1 = x @ W1 (f32x2), fused a_src/a_dst projections ----------------
__global__ void k_gemm1(const float* __restrict__ x, const float* __restrict__ W1,
                        const float* __restrict__ as1, const float* __restrict__ ad1) {
    __shared__ float xs[4][F_IN];
    int t = threadIdx.x, y = threadIdx.y;
    int node = blockIdx.x * 4 + y;
    xs[y][t]      = x[node * F_IN + t];
    xs[y][t + 64] = x[node * F_IN + t + 64];
    __syncthreads();
    const float4* W1v = (const float4*)W1;
    unsigned long long a01 = 0ull, a23 = 0ull;
#pragma unroll 8
    for (int k = 0; k < F_IN; k++) {
        float xv = xs[y][k];
        unsigned long long xp = pk2(xv, xv);
        float4 w = W1v[k * 64 + t];
        ffma2(a01, xp, pk2(w.x, w.y));
        ffma2(a23, xp, pk2(w.z, w.w));
    }
    float2 axy = upk2(a01), azw = upk2(a23);
    float4 acc = make_float4(axy.x, axy.y, azw.x, azw.y);
    ((float4*)g_h1)[node * 64 + t] = acc;
    int c0 = 4 * t;
    float ps = acc.x * as1[c0] + acc.y * as1[c0 + 1] + acc.z * as1[c0 + 2] + acc.w * as1[c0 + 3];
    float pd = acc.x * ad1[c0] + acc.y * ad1[c0 + 1] + acc.z * ad1[c0 + 2] + acc.w * ad1[c0 + 3];
#pragma unroll
    for (int off = 8; off; off >>= 1) {
        ps += __shfl_xor_sync(0xffffffffu, ps, off, 16);
        pd += __shfl_xor_sync(0xffffffffu, pd, off, 16);
    }
    if ((t & 15) == 0) {
        int h = t >> 4;
        g_als1[node * H1 + h] = ps;
        g_ald1[node * H1 + h] = pd;
    }
}

// ---------------- fused GAT layer 1: 2 warps per dst node (channel halves), unroll 4 ----------------
__global__ void k_gat1() {
    int gw = (blockIdx.x * blockDim.x + threadIdx.x) >> 5;
    int lane = threadIdx.x & 31;
    int d = gw >> 1, half = gw & 1;
    if (d >= N_NODES) return;
    int beg = g_ptr[d], end = g_ptr[d + 1];
    float4 ald4 = ((const float4*)g_ald1)[d];
    bool lo = lane < 16;
    // this warp covers float4 index ci = half*32+lane -> channels [4*ci,4*ci+3]
    // head of channel c is c>>6: for half 0: lanes 0-15 head0, 16-31 head1; half 1: head2/head3
    float ad = half ? (lo ? ald4.z : ald4.w) : (lo ? ald4.x : ald4.y);
    int ci = half * 32 + lane;

    float4 acc = make_float4(0.f, 0.f, 0.f, 0.f);
    float ssum = 0.f;
    int i = beg;
    for (; i + 4 <= end; i += 4) {
        int s0 = __ldg(&g_csr[i]);
        int s1 = __ldg(&g_csr[i + 1]);
        int s2 = __ldg(&g_csr[i + 2]);
        int s3 = __ldg(&g_csr[i + 3]);
        float4 a0 = ((const float4*)g_als1)[s0];
        float4 a1 = ((const float4*)g_als1)[s1];
        float4 a2 = ((const float4*)g_als1)[s2];
        float4 a3 = ((const float4*)g_als1)[s3];
        float4 h0 = ((const float4*)(g_h1 + (size_t)s0 * HC1))[ci];
        float4 h1 = ((const float4*)(g_h1 + (size_t)s1 * HC1))[ci];
        float4 h2 = ((const float4*)(g_h1 + (size_t)s2 * HC1))[ci];
        float4 h3 = ((const float4*)(g_h1 + (size_t)s3 * HC1))[ci];
        float w0 = __expf(lrelu((half ? (lo ? a0.z : a0.w) : (lo ? a0.x : a0.y)) + ad));
        float w1 = __expf(lrelu((half ? (lo ? a1.z : a1.w) : (lo ? a1.x : a1.y)) + ad));
        float w2 = __expf(lrelu((half ? (lo ? a2.z : a2.w) : (lo ? a2.x : a2.y)) + ad));
        float w3 = __expf(lrelu((half ? (lo ? a3.z : a3.w) : (lo ? a3.x : a3.y)) + ad));
        ssum += (w0 + w1) + (w2 + w3);
        acc.x += w0 * h0.x + w1 * h1.x + w2 * h2.x + w3 * h3.x;
        acc.y += w0 * h0.y + w1 * h1.y + w2 * h2.y + w3 * h3.y;
        acc.z += w0 * h0.z + w1 * h1.z + w2 * h2.z + w3 * h3.z;
        acc.w += w0 * h0.w + w1 * h1.w + w2 * h2.w + w3 * h3.w;
    }
    for (; i < end; i++) {
        int s = __ldg(&g_csr[i]);
        float4 a = ((const float4*)g_als1)[s];
        float4 h = ((const float4*)(g_h1 + (size_t)s * HC1))[ci];
        float w = __expf(lrelu((half ? (lo ? a.z : a.w) : (lo ? a.x : a.y)) + ad));
        ssum += w;
        acc.x += w * h.x; acc.y += w * h.y; acc.z += w * h.z; acc.w += w * h.w;
    }
    float inv = 1.f / (ssum + 1e-16f);
    acc.x *= inv; acc.y *= inv; acc.z *= inv; acc.w *= inv;
    ((float4*)(g_out1 + (size_t)d * HC1))[ci] = acc;
}

// ---------------- GEMM2: h2 = relu(out1 + b1) @ W2 (f32x2), fused projections ----------------
__global__ void k_gemm2(const float* __restrict__ W2, const float* __restrict__ b1,
                        const float* __restrict__ as2, const float* __restrict__ ad2) {
    __shared__ float rs[8][HC1];
    int t = threadIdx.x, y = threadIdx.y;
    int tid = t + 16 * y;
    int nodeBase = blockIdx.x * 8;
    for (int idx = tid; idx < 8 * HC1; idx += 128) {
        int nl = idx >> 8, k = idx & 255;
        float v = g_out1[(size_t)(nodeBase + nl) * HC1 + k] + b1[k];
        rs[nl][k] = v > 0.f ? v : 0.f;
    }
    __syncthreads();
    int node = nodeBase + y;
    const float4* W2v = (const float4*)W2;
    unsigned long long a01 = 0ull, a23 = 0ull;
#pragma unroll 8
    for (int k = 0; k < HC1; k++) {
        float rv = rs[y][k];
        unsigned long long xp = pk2(rv, rv);
        float4 w = W2v[k * 16 + t];
        ffma2(a01, xp, pk2(w.x, w.y));
        ffma2(a23, xp, pk2(w.z, w.w));
    }
    float2 axy = upk2(a01), azw = upk2(a23);
    float4 acc = make_float4(axy.x, axy.y, azw.x, azw.y);
    ((float4*)g_h2)[node * 16 + t] = acc;
    int c0 = 4 * t;
    float ps = acc.x * as2[c0] + acc.y * as2[c0 + 1] + acc.z * as2[c0 + 2] + acc.w * as2[c0 + 3];
    float pd = acc.x * ad2[c0] + acc.y * ad2[c0 + 1] + acc.z * ad2[c0 + 2] + acc.w * ad2[c0 + 3];
#pragma unroll
    for (int off = 8; off; off >>= 1) {
        ps += __shfl_xor_sync(0xffffffffu, ps, off, 16);
        pd += __shfl_xor_sync(0xffffffffu, pd, off, 16);
    }
    if (t == 0) { g_als2[node] = ps; g_ald2[node] = pd; }
}

// ---------------- fused GAT layer 2 + pool scatter: warp per dst node, unroll 4 ----------------
__global__ void k_gat2(const int* __restrict__ bat) {
    int warp = (blockIdx.x * blockDim.x + threadIdx.x) >> 5;
    int lane = threadIdx.x & 31;
    if (warp >= N_NODES) return;
    int d = warp;
    int beg = g_ptr[d], end = g_ptr[d + 1];
    float ald = g_ald2[d];

    float2 acc = make_float2(0.f, 0.f);
    float ssum = 0.f;
    int i = beg;
    for (; i + 4 <= end; i += 4) {
        int s0 = __ldg(&g_csr[i]);
        int s1 = __ldg(&g_csr[i + 1]);
        int s2 = __ldg(&g_csr[i + 2]);
        int s3 = __ldg(&g_csr[i + 3]);
        float a0 = g_als2[s0];
        float a1 = g_als2[s1];
        float a2 = g_als2[s2];
        float a3 = g_als2[s3];
        float2 h0 = ((const float2*)(g_h2 + (size_t)s0 * C2))[lane];
        float2 h1 = ((const float2*)(g_h2 + (size_t)s1 * C2))[lane];
        float2 h2 = ((const float2*)(g_h2 + (size_t)s2 * C2))[lane];
        float2 h3 = ((const float2*)(g_h2 + (size_t)s3 * C2))[lane];
        float w0 = __expf(lrelu(a0 + ald));
        float w1 = __expf(lrelu(a1 + ald));
        float w2 = __expf(lrelu(a2 + ald));
        float w3 = __expf(lrelu(a3 + ald));
        ssum += (w0 + w1) + (w2 + w3);
        acc.x += w0 * h0.x + w1 * h1.x + w2 * h2.x + w3 * h3.x;
        acc.y += w0 * h0.y + w1 * h1.y + w2 * h2.y + w3 * h3.y;
    }
    for (; i < end; i++) {
        int s = __ldg(&g_csr[i]);
        float w = __expf(lrelu(g_als2[s] + ald));
        float2 h = ((const float2*)(g_h2 + (size_t)s * C2))[lane];
        ssum += w;
        acc.x += w * h.x;
        acc.y += w * h.y;
    }
    float inv = 1.f / (ssum + 1e-16f);
    int g = bat[d];
    red_add_v2(g_pool + g * C2 + 2 * lane, acc.x * inv, acc.y * inv);
}

// ---------------- classifier + log_softmax (b2 folded via node counts) ----------------
__global__ void k_cls(const float* __restrict__ fcw, const float* __restrict__ fcb,
                      const float* __restrict__ b2, float* __restrict__ out) {
    int g = blockIdx.x;
    int t = threadIdx.x;
    __shared__ float lg[NCLS];
    __shared__ float s_m, s_lse;
    if (t < NCLS) {
        float cnt = (float)g_cnt[g];
        float acc = fcb[t];
#pragma unroll
        for (int k = 0; k < C2; k++)
            acc += (g_pool[g * C2 + k] + cnt * b2[k]) * fcw[k * NCLS + t];
        lg[t] = acc;
    }
    __syncthreads();
    if (t == 0) {
        float m = lg[0];
        for (int i = 1; i < NCLS; i++) m = fmaxf(m, lg[i]);
        float s = 0.f;
        for (int i = 0; i < NCLS; i++) s += expf(lg[i] - m);
        s_m = m; s_lse = logf(s);
    }
    __syncthreads();
    if (t < NCLS) out[g * NCLS + t] = lg[t] - s_m - s_lse;
}

// ---------------- launch ----------------
extern "C" void kernel_launch(void* const* d_in, const int* in_sizes, int n_in,
                              void* d_out, int out_size) {
    const float* x    = (const float*)d_in[0];
    const int*   ei   = (const int*)d_in[1];
    const int*   bat  = (const int*)d_in[2];
    const float* W1   = (const float*)d_in[3];
    const float* as1  = (const float*)d_in[4];
    const float* ad1  = (const float*)d_in[5];
    const float* b1   = (const float*)d_in[6];
    const float* W2   = (const float*)d_in[7];
    const float* as2  = (const float*)d_in[8];
    const float* ad2  = (const float*)d_in[9];
    const float* b2   = (const float*)d_in[10];
    const float* fcw  = (const float*)d_in[11];
    const float* fcb  = (const float*)d_in[12];
    float* out = (float*)d_out;

    int eb = (E_TOT + 255) / 256;
    k_init<<<(N_NODES + 255) / 256, 256>>>();
    k_deg<<<eb, 256>>>(ei, bat);
    k_scan<<<1, SCAN_T>>>();
    k_fill<<<eb, 256>>>(ei);
    k_gemm1<<<N_NODES / 4, dim3(64, 4)>>>(x, W1, as1, ad1);
    k_gat1<<<(N_NODES * 2 * 32 + 255) / 256, 256>>>();
    k_gemm2<<<N_NODES / 8, dim3(16, 8)>>>(W2, b1, as2, ad2);
    k_gat2<<<(N_NODES * 32 + 255) / 256, 256>>>(bat);
    k_cls<<<NGRAPH, 32>>>(fcw, fcb, b2, out);
}